// round 2
// baseline (speedup 1.0000x reference)
#include <cuda_runtime.h>
#include <math.h>
#include <stdint.h>

// Problem constants (fixed by reference)
#define N_NODES 50000
#define N_HPREV 256
#define N_HID   128
#define NNZ_C   800000
#define LN_EPS  1e-5f

// ---------------------------------------------------------------------------
// Scratch: 4 state buffers [N_NODES, N_HID] fp32 (device globals: no mallocs)
// ---------------------------------------------------------------------------
__device__ __align__(16) float g_s0[(size_t)N_NODES * N_HID];
__device__ __align__(16) float g_s1[(size_t)N_NODES * N_HID];
__device__ __align__(16) float g_s2[(size_t)N_NODES * N_HID];
__device__ __align__(16) float g_s3[(size_t)N_NODES * N_HID];

__device__ __forceinline__ float* state_ptr(int s) {
    switch (s) {
        case 0:  return g_s0;
        case 1:  return g_s1;
        case 2:  return g_s2;
        default: return g_s3;
    }
}

// ---------------------------------------------------------------------------
// Zero the three accumulator states (s1, s2, s3)
// ---------------------------------------------------------------------------
__global__ void zero_states_kernel(int n4) {
    int i = blockIdx.x * blockDim.x + threadIdx.x;
    if (i < n4) {
        float4 z = make_float4(0.f, 0.f, 0.f, 0.f);
        reinterpret_cast<float4*>(g_s1)[i] = z;
        reinterpret_cast<float4*>(g_s2)[i] = z;
        reinterpret_cast<float4*>(g_s3)[i] = z;
    }
}

// ---------------------------------------------------------------------------
// GEMM: g_s0 = x @ W + b      x:[M,256]  W:[256,128]  b:[128]
// 128x128 block tile, BK=32, 256 threads, 8x8 per-thread microtile.
// ---------------------------------------------------------------------------
#define BM 128
#define BK 32

__global__ __launch_bounds__(256) void gemm_bias_kernel(
    const float* __restrict__ A, const float* __restrict__ W,
    const float* __restrict__ bias, int M)
{
    __shared__ float As[BM][BK + 4];   // +4 pad keeps float4 STS aligned
    __shared__ float Bs[BK][N_HID];

    int tid  = threadIdx.x;
    int row0 = blockIdx.x * BM;

    int tx = tid & 15;       // 16 col-groups of 8
    int ty = tid >> 4;       // 16 row-groups of 8

    float acc[8][8];
#pragma unroll
    for (int i = 0; i < 8; ++i)
#pragma unroll
        for (int j = 0; j < 8; ++j) acc[i][j] = 0.f;

    // A-load mapping: each thread loads float4 along k; 32 rows x 8 k-groups
    int am = tid >> 3;             // 0..31 (row within 32-row pass)
    int ak = (tid & 7) * 4;        // 0,4,...,28
    // B-load mapping: float4 along n; 8 k-rows per pass
    int bk = tid >> 5;             // 0..7
    int bn = (tid & 31) * 4;       // 0..124

    for (int k0 = 0; k0 < N_HPREV; k0 += BK) {
#pragma unroll
        for (int mm = 0; mm < BM; mm += 32) {
            int gr = row0 + am + mm;
            float4 v = make_float4(0.f, 0.f, 0.f, 0.f);
            if (gr < M)
                v = *reinterpret_cast<const float4*>(A + (size_t)gr * N_HPREV + k0 + ak);
            *reinterpret_cast<float4*>(&As[am + mm][ak]) = v;
        }
#pragma unroll
        for (int kk = 0; kk < BK; kk += 8) {
            float4 v = *reinterpret_cast<const float4*>(
                W + (size_t)(k0 + bk + kk) * N_HID + bn);
            *reinterpret_cast<float4*>(&Bs[bk + kk][bn]) = v;
        }
        __syncthreads();

#pragma unroll
        for (int k = 0; k < BK; ++k) {
            float a[8], bb[8];
#pragma unroll
            for (int i = 0; i < 8; ++i) a[i] = As[ty * 8 + i][k];
            float4 b0 = *reinterpret_cast<float4*>(&Bs[k][tx * 8]);
            float4 b1 = *reinterpret_cast<float4*>(&Bs[k][tx * 8 + 4]);
            bb[0] = b0.x; bb[1] = b0.y; bb[2] = b0.z; bb[3] = b0.w;
            bb[4] = b1.x; bb[5] = b1.y; bb[6] = b1.z; bb[7] = b1.w;
#pragma unroll
            for (int i = 0; i < 8; ++i)
#pragma unroll
                for (int j = 0; j < 8; ++j) acc[i][j] += a[i] * bb[j];
        }
        __syncthreads();
    }

    // epilogue: + bias, store to g_s0
    float4 bia0 = *reinterpret_cast<const float4*>(bias + tx * 8);
    float4 bia1 = *reinterpret_cast<const float4*>(bias + tx * 8 + 4);
    float bi[8] = {bia0.x, bia0.y, bia0.z, bia0.w, bia1.x, bia1.y, bia1.z, bia1.w};

#pragma unroll
    for (int i = 0; i < 8; ++i) {
        int gr = row0 + ty * 8 + i;
        if (gr < M) {
            float4 o0 = make_float4(acc[i][0] + bi[0], acc[i][1] + bi[1],
                                    acc[i][2] + bi[2], acc[i][3] + bi[3]);
            float4 o1 = make_float4(acc[i][4] + bi[4], acc[i][5] + bi[5],
                                    acc[i][6] + bi[6], acc[i][7] + bi[7]);
            *reinterpret_cast<float4*>(g_s0 + (size_t)gr * N_HID + tx * 8)     = o0;
            *reinterpret_cast<float4*>(g_s0 + (size_t)gr * N_HID + tx * 8 + 4) = o1;
        }
    }
}

// ---------------------------------------------------------------------------
// Vector reduction to global memory: 8 floats starting at p (16B-aligned).
// Uses red.global.add.v2.f32 (PTX ISA 8.1+, sm_90+).
// ---------------------------------------------------------------------------
__device__ __forceinline__ void red_add_f32x4(float* p, float4 v) {
#if __CUDA_ARCH__ >= 900
    asm volatile("red.global.add.v2.f32 [%0], {%1, %2};"
                 :: "l"(p), "f"(v.x), "f"(v.y) : "memory");
    asm volatile("red.global.add.v2.f32 [%0], {%1, %2};"
                 :: "l"(p + 2), "f"(v.z), "f"(v.w) : "memory");
#else
    atomicAdd(p + 0, v.x);
    atomicAdd(p + 1, v.y);
    atomicAdd(p + 2, v.z);
    atomicAdd(p + 3, v.w);
#endif
}

// ---------------------------------------------------------------------------
// Fused SpMM step: dst += sum_t spmm(adj[*idx_t], src_t)
// One warp per nonzero. Lane l handles 4 of the 128 columns (float4).
// ---------------------------------------------------------------------------
__global__ __launch_bounds__(256) void spmm_step_kernel(
    const int*   __restrict__ adj_rows,
    const int*   __restrict__ adj_cols,
    const float* __restrict__ adj_vals,
    const int* idxp0, const int* idxp1, const int* idxp2,
    int src0, int src1, int src2,
    int n_terms, int dst_id)
{
    int wid  = (blockIdx.x * blockDim.x + threadIdx.x) >> 5;
    int lane = threadIdx.x & 31;
    long total = (long)n_terms * NNZ_C;
    if (wid >= total) return;

    int t = wid / NNZ_C;          // term index 0..2
    int i = wid - t * NNZ_C;      // nnz index within adjacency

    const int* idxp = (t == 0) ? idxp0 : ((t == 1) ? idxp1 : idxp2);
    int srcid       = (t == 0) ? src0  : ((t == 1) ? src1  : src2);

    int a = __ldg(idxp);          // adjacency selector (broadcast load)
    const float* __restrict__ src = state_ptr(srcid);
    float*       __restrict__ dst = state_ptr(dst_id);

    size_t base = (size_t)a * NNZ_C + (size_t)i;
    int   r = __ldg(adj_rows + base);
    int   c = __ldg(adj_cols + base);
    float v = __ldg(adj_vals + base);

    float4 xv = *reinterpret_cast<const float4*>(src + (size_t)c * N_HID + lane * 4);
    float4 yv = make_float4(xv.x * v, xv.y * v, xv.z * v, xv.w * v);

    red_add_f32x4(dst + (size_t)r * N_HID + lane * 4, yv);
}

// ---------------------------------------------------------------------------
// LayerNorm (over 128) + exact-erf GELU.  One warp per row, 4 cols per lane.
// ---------------------------------------------------------------------------
__device__ __forceinline__ float gelu_exact(float x) {
    return 0.5f * x * (1.f + erff(x * 0.70710678118654752440f));
}

__global__ __launch_bounds__(256) void ln_gelu_kernel(
    const float* __restrict__ gamma, const float* __restrict__ beta,
    float* __restrict__ out)
{
    int row  = blockIdx.x * (blockDim.x >> 5) + (threadIdx.x >> 5);
    int lane = threadIdx.x & 31;
    if (row >= N_NODES) return;

    float4 v = *reinterpret_cast<const float4*>(g_s3 + (size_t)row * N_HID + lane * 4);
    float s  = v.x + v.y + v.z + v.w;
    float sq = v.x * v.x + v.y * v.y + v.z * v.z + v.w * v.w;
#pragma unroll
    for (int o = 16; o > 0; o >>= 1) {
        s  += __shfl_xor_sync(0xFFFFFFFFu, s, o);
        sq += __shfl_xor_sync(0xFFFFFFFFu, sq, o);
    }
    float mu  = s * (1.f / N_HID);
    float var = sq * (1.f / N_HID) - mu * mu;
    float rs  = rsqrtf(var + LN_EPS);

    float4 g  = *reinterpret_cast<const float4*>(gamma + lane * 4);
    float4 be = *reinterpret_cast<const float4*>(beta  + lane * 4);

    float4 o;
    o.x = gelu_exact((v.x - mu) * rs * g.x + be.x);
    o.y = gelu_exact((v.y - mu) * rs * g.y + be.y);
    o.z = gelu_exact((v.z - mu) * rs * g.z + be.z);
    o.w = gelu_exact((v.w - mu) * rs * g.w + be.w);
    *reinterpret_cast<float4*>(out + (size_t)row * N_HID + lane * 4) = o;
}

// ---------------------------------------------------------------------------
// Launch
// inputs: 0:x 1:adj_rows 2:adj_cols 3:adj_vals 4:idxes_seq 5:idxes_res
//         6:W 7:b 8:gamma 9:beta        out: [50000,128] f32
// ---------------------------------------------------------------------------
extern "C" void kernel_launch(void* const* d_in, const int* in_sizes, int n_in,
                              void* d_out, int out_size)
{
    const float* x        = (const float*)d_in[0];
    const int*   adj_rows = (const int*)  d_in[1];
    const int*   adj_cols = (const int*)  d_in[2];
    const float* adj_vals = (const float*)d_in[3];
    const int*   seq      = (const int*)  d_in[4];
    const int*   res      = (const int*)  d_in[5];
    const float* W        = (const float*)d_in[6];
    const float* b        = (const float*)d_in[7];
    const float* gamma    = (const float*)d_in[8];
    const float* beta     = (const float*)d_in[9];
    float*       out      = (float*)d_out;

    // zero accumulators s1..s3
    {
        int n4 = (N_NODES * N_HID) / 4;    // 1.6M float4 per buffer
        zero_states_kernel<<<(n4 + 255) / 256, 256>>>(n4);
    }

    // s0 = x @ W + b
    gemm_bias_kernel<<<(N_NODES + BM - 1) / BM, 256>>>(x, W, b, N_NODES);

    // step 0: s1 = spmm(seq[0], s0)
    {
        long total = 1L * NNZ_C;
        int blocks = (int)((total * 32 + 255) / 256);
        spmm_step_kernel<<<blocks, 256>>>(adj_rows, adj_cols, adj_vals,
                                          seq + 0, nullptr, nullptr,
                                          0, 0, 0, 1, 1);
    }
    // step 1: s2 = spmm(seq[1], s1) + spmm(res[0], s0)
    {
        long total = 2L * NNZ_C;
        int blocks = (int)((total * 32 + 255) / 256);
        spmm_step_kernel<<<blocks, 256>>>(adj_rows, adj_cols, adj_vals,
                                          seq + 1, res + 0, nullptr,
                                          1, 0, 0, 2, 2);
    }
    // step 2: s3 = spmm(seq[2], s2) + spmm(res[1], s0) + spmm(res[2], s1)
    {
        long total = 3L * NNZ_C;
        int blocks = (int)((total * 32 + 255) / 256);
        spmm_step_kernel<<<blocks, 256>>>(adj_rows, adj_cols, adj_vals,
                                          seq + 2, res + 1, res + 2,
                                          2, 0, 1, 3, 3);
    }

    // out = gelu(layernorm(s3))
    ln_gelu_kernel<<<(N_NODES + 7) / 8, 256>>>(gamma, beta, out);
}

// round 5
// speedup vs baseline: 1.8363x; 1.8363x over previous
#include <cuda_runtime.h>
#include <math.h>
#include <stdint.h>

// Problem constants (fixed by reference)
#define N_NODES 50000
#define N_HPREV 256
#define N_HID   128
#define NNZ_C   800000
#define N_ADJ   6
#define LN_EPS  1e-5f

#define SCAN_BLK 1024
#define NCHUNK   ((N_NODES + SCAN_BLK - 1) / SCAN_BLK)   // 49

// ---------------------------------------------------------------------------
// Scratch (device globals; referenced ONLY from device code)
// ---------------------------------------------------------------------------
__device__ __align__(16) float g_s0[(size_t)N_NODES * N_HID];   // 25.6 MB
__device__ __align__(16) float g_s1[(size_t)N_NODES * N_HID];   // 25.6 MB
__device__ __align__(16) float g_s2[(size_t)N_NODES * N_HID];   // 25.6 MB

__device__ int g_ptr [N_ADJ * (N_NODES + 1)];   // CSR row pointers
__device__ int g_fill[N_ADJ * N_NODES];         // histogram, then scatter cursors
__device__ int g_bsum[N_ADJ * NCHUNK];          // per-chunk scan sums
__device__ __align__(16) int g_perm[(size_t)N_ADJ * NNZ_C];   // 19.2 MB

__device__ __forceinline__ float* state_ptr(int s) {
    switch (s) {
        case 0:  return g_s0;
        case 1:  return g_s1;
        default: return g_s2;
    }
}

// ---------------------------------------------------------------------------
// CSR build phase 0: zero the histogram (g_fill doubles as cnt)
// ---------------------------------------------------------------------------
__global__ __launch_bounds__(256) void zero_cnt_kernel() {
    int i = blockIdx.x * blockDim.x + threadIdx.x;
    if (i < N_ADJ * N_NODES) g_fill[i] = 0;
}

// phase 1: histogram rows
__global__ __launch_bounds__(256) void hist_kernel(const int* __restrict__ rows) {
    int e = blockIdx.x * blockDim.x + threadIdx.x;
    if (e >= N_ADJ * NNZ_C) return;
    int a = e / NNZ_C;
    int r = __ldg(rows + e);
    atomicAdd(&g_fill[a * N_NODES + r], 1);
}

// phase 2: per-chunk inclusive scan of counts (partials into g_ptr)
__global__ __launch_bounds__(SCAN_BLK) void scan_phase1_kernel() {
    __shared__ int sh[SCAN_BLK];
    int a     = blockIdx.y;
    int chunk = blockIdx.x;
    int tid   = threadIdx.x;
    int i     = chunk * SCAN_BLK + tid;

    int v = (i < N_NODES) ? g_fill[a * N_NODES + i] : 0;
    sh[tid] = v;
    __syncthreads();
#pragma unroll
    for (int off = 1; off < SCAN_BLK; off <<= 1) {
        int t = (tid >= off) ? sh[tid - off] : 0;
        __syncthreads();
        sh[tid] += t;
        __syncthreads();
    }
    if (i < N_NODES) g_ptr[a * (N_NODES + 1) + i] = sh[tid];   // inclusive partial
    if (tid == SCAN_BLK - 1) g_bsum[a * NCHUNK + chunk] = sh[tid];
}

// phase 3: exclusive scan of chunk sums (serial, tiny)
__global__ void scan_phase2_kernel() {
    int a = threadIdx.x;
    if (a >= N_ADJ) return;
    int run = 0;
    for (int c = 0; c < NCHUNK; ++c) {
        int t = g_bsum[a * NCHUNK + c];
        g_bsum[a * NCHUNK + c] = run;
        run += t;
    }
}

// phase 4: finalize exclusive row pointers + init scatter cursors
__global__ __launch_bounds__(SCAN_BLK) void scan_phase3_kernel() {
    int a     = blockIdx.y;
    int chunk = blockIdx.x;
    int tid   = threadIdx.x;
    int i     = chunk * SCAN_BLK + tid;
    if (i < N_NODES) {
        int incl = g_ptr[a * (N_NODES + 1) + i];
        int cnt  = g_fill[a * N_NODES + i];
        int excl = incl - cnt + g_bsum[a * NCHUNK + chunk];
        g_ptr [a * (N_NODES + 1) + i] = excl;
        g_fill[a * N_NODES + i]       = excl;
    }
    if (blockIdx.x == 0 && tid == 0)
        g_ptr[a * (N_NODES + 1) + N_NODES] = NNZ_C;
}

// phase 5: scatter original nnz index into CSR order (perm only, 4B/nnz)
__global__ __launch_bounds__(256) void scatter_kernel(const int* __restrict__ rows) {
    int e = blockIdx.x * blockDim.x + threadIdx.x;
    if (e >= N_ADJ * NNZ_C) return;
    int a = e / NNZ_C;
    int r = __ldg(rows + e);
    int pos = atomicAdd(&g_fill[a * N_NODES + r], 1);
    g_perm[(size_t)a * NNZ_C + pos] = e - a * NNZ_C;   // index within adjacency
}

// ---------------------------------------------------------------------------
// GEMM: g_s0 = x @ W + b      x:[M,256]  W:[256,128]  b:[128]
// ---------------------------------------------------------------------------
#define BM 128
#define BK 32

__global__ __launch_bounds__(256) void gemm_bias_kernel(
    const float* __restrict__ A, const float* __restrict__ W,
    const float* __restrict__ bias, int M)
{
    __shared__ float As[BM][BK + 4];
    __shared__ float Bs[BK][N_HID];

    int tid  = threadIdx.x;
    int row0 = blockIdx.x * BM;

    int tx = tid & 15;
    int ty = tid >> 4;

    float acc[8][8];
#pragma unroll
    for (int i = 0; i < 8; ++i)
#pragma unroll
        for (int j = 0; j < 8; ++j) acc[i][j] = 0.f;

    int am = tid >> 3;
    int ak = (tid & 7) * 4;
    int bk = tid >> 5;
    int bn = (tid & 31) * 4;

    for (int k0 = 0; k0 < N_HPREV; k0 += BK) {
#pragma unroll
        for (int mm = 0; mm < BM; mm += 32) {
            int gr = row0 + am + mm;
            float4 v = make_float4(0.f, 0.f, 0.f, 0.f);
            if (gr < M)
                v = *reinterpret_cast<const float4*>(A + (size_t)gr * N_HPREV + k0 + ak);
            *reinterpret_cast<float4*>(&As[am + mm][ak]) = v;
        }
#pragma unroll
        for (int kk = 0; kk < BK; kk += 8) {
            float4 v = *reinterpret_cast<const float4*>(
                W + (size_t)(k0 + bk + kk) * N_HID + bn);
            *reinterpret_cast<float4*>(&Bs[bk + kk][bn]) = v;
        }
        __syncthreads();

#pragma unroll
        for (int k = 0; k < BK; ++k) {
            float a[8], bb[8];
#pragma unroll
            for (int i = 0; i < 8; ++i) a[i] = As[ty * 8 + i][k];
            float4 b0 = *reinterpret_cast<float4*>(&Bs[k][tx * 8]);
            float4 b1 = *reinterpret_cast<float4*>(&Bs[k][tx * 8 + 4]);
            bb[0] = b0.x; bb[1] = b0.y; bb[2] = b0.z; bb[3] = b0.w;
            bb[4] = b1.x; bb[5] = b1.y; bb[6] = b1.z; bb[7] = b1.w;
#pragma unroll
            for (int i = 0; i < 8; ++i)
#pragma unroll
                for (int j = 0; j < 8; ++j) acc[i][j] += a[i] * bb[j];
        }
        __syncthreads();
    }

    float4 bia0 = *reinterpret_cast<const float4*>(bias + tx * 8);
    float4 bia1 = *reinterpret_cast<const float4*>(bias + tx * 8 + 4);
    float bi[8] = {bia0.x, bia0.y, bia0.z, bia0.w, bia1.x, bia1.y, bia1.z, bia1.w};

#pragma unroll
    for (int i = 0; i < 8; ++i) {
        int gr = row0 + ty * 8 + i;
        if (gr < M) {
            float4 o0 = make_float4(acc[i][0] + bi[0], acc[i][1] + bi[1],
                                    acc[i][2] + bi[2], acc[i][3] + bi[3]);
            float4 o1 = make_float4(acc[i][4] + bi[4], acc[i][5] + bi[5],
                                    acc[i][6] + bi[6], acc[i][7] + bi[7]);
            *reinterpret_cast<float4*>(g_s0 + (size_t)gr * N_HID + tx * 8)     = o0;
            *reinterpret_cast<float4*>(g_s0 + (size_t)gr * N_HID + tx * 8 + 4) = o1;
        }
    }
}

// ---------------------------------------------------------------------------
// CSR SpMM step: warp per output row, register accumulate, single store.
// Destination: state buffer (dst_id, resolved in-kernel) or final_out with
// fused LayerNorm + exact-erf GELU when do_ln != 0.
// ---------------------------------------------------------------------------
__device__ __forceinline__ float gelu_exact(float x) {
    return 0.5f * x * (1.f + erff(x * 0.70710678118654752440f));
}

__global__ __launch_bounds__(256) void spmm_csr_step_kernel(
    const int*   __restrict__ adj_cols,
    const float* __restrict__ adj_vals,
    const int* idxp0, const int* idxp1, const int* idxp2,
    int src0, int src1, int src2, int n_terms,
    int dst_id,                         // used when do_ln == 0
    float* __restrict__ final_out,      // used when do_ln == 1 (harness d_out)
    int do_ln,
    const float* __restrict__ gamma, const float* __restrict__ beta)
{
    int row  = blockIdx.x * (blockDim.x >> 5) + (threadIdx.x >> 5);
    int lane = threadIdx.x & 31;
    if (row >= N_NODES) return;

    float4 acc = make_float4(0.f, 0.f, 0.f, 0.f);

#pragma unroll 1
    for (int t = 0; t < n_terms; ++t) {
        const int* idxp = (t == 0) ? idxp0 : ((t == 1) ? idxp1 : idxp2);
        int srcid       = (t == 0) ? src0  : ((t == 1) ? src1  : src2);
        int a = __ldg(idxp);
        const float* __restrict__ src  = state_ptr(srcid);
        const int*   __restrict__ perm = g_perm + (size_t)a * NNZ_C;
        const int*   __restrict__ cols = adj_cols + (size_t)a * NNZ_C;
        const float* __restrict__ vals = adj_vals + (size_t)a * NNZ_C;

        int s = __ldg(&g_ptr[a * (N_NODES + 1) + row]);
        int e = __ldg(&g_ptr[a * (N_NODES + 1) + row + 1]);

        for (int base = s; base < e; base += 32) {
            int j = base + lane;
            int   c = 0;
            float v = 0.f;
            if (j < e) {
                int p = __ldg(perm + j);
                c = __ldg(cols + p);
                v = __ldg(vals + p);
            }
            int m = min(32, e - base);
#pragma unroll 4
            for (int k = 0; k < m; ++k) {
                int   ck = __shfl_sync(0xFFFFFFFFu, c, k);
                float vk = __shfl_sync(0xFFFFFFFFu, v, k);
                float4 xv = *reinterpret_cast<const float4*>(
                    src + (size_t)ck * N_HID + lane * 4);
                acc.x += vk * xv.x;
                acc.y += vk * xv.y;
                acc.z += vk * xv.z;
                acc.w += vk * xv.w;
            }
        }
    }

    if (do_ln) {
        float s  = acc.x + acc.y + acc.z + acc.w;
        float sq = acc.x * acc.x + acc.y * acc.y + acc.z * acc.z + acc.w * acc.w;
#pragma unroll
        for (int o = 16; o > 0; o >>= 1) {
            s  += __shfl_xor_sync(0xFFFFFFFFu, s, o);
            sq += __shfl_xor_sync(0xFFFFFFFFu, sq, o);
        }
        float mu  = s * (1.f / N_HID);
        float var = sq * (1.f / N_HID) - mu * mu;
        float rs  = rsqrtf(var + LN_EPS);

        float4 g  = *reinterpret_cast<const float4*>(gamma + lane * 4);
        float4 be = *reinterpret_cast<const float4*>(beta  + lane * 4);

        float4 o;
        o.x = gelu_exact((acc.x - mu) * rs * g.x + be.x);
        o.y = gelu_exact((acc.y - mu) * rs * g.y + be.y);
        o.z = gelu_exact((acc.z - mu) * rs * g.z + be.z);
        o.w = gelu_exact((acc.w - mu) * rs * g.w + be.w);
        *reinterpret_cast<float4*>(final_out + (size_t)row * N_HID + lane * 4) = o;
    } else {
        float* dst = state_ptr(dst_id);
        *reinterpret_cast<float4*>(dst + (size_t)row * N_HID + lane * 4) = acc;
    }
}

// ---------------------------------------------------------------------------
// Launch
// inputs: 0:x 1:adj_rows 2:adj_cols 3:adj_vals 4:idxes_seq 5:idxes_res
//         6:W 7:b 8:gamma 9:beta        out: [50000,128] f32
// ---------------------------------------------------------------------------
extern "C" void kernel_launch(void* const* d_in, const int* in_sizes, int n_in,
                              void* d_out, int out_size)
{
    const float* x        = (const float*)d_in[0];
    const int*   adj_rows = (const int*)  d_in[1];
    const int*   adj_cols = (const int*)  d_in[2];
    const float* adj_vals = (const float*)d_in[3];
    const int*   seq      = (const int*)  d_in[4];
    const int*   res      = (const int*)  d_in[5];
    const float* W        = (const float*)d_in[6];
    const float* b        = (const float*)d_in[7];
    const float* gamma    = (const float*)d_in[8];
    const float* beta     = (const float*)d_in[9];
    float*       out      = (float*)d_out;

    // ---- CSR build (all 6 adjacencies) ----
    zero_cnt_kernel<<<(N_ADJ * N_NODES + 255) / 256, 256>>>();
    hist_kernel<<<(N_ADJ * NNZ_C + 255) / 256, 256>>>(adj_rows);
    {
        dim3 grid(NCHUNK, N_ADJ);
        scan_phase1_kernel<<<grid, SCAN_BLK>>>();
        scan_phase2_kernel<<<1, 32>>>();
        scan_phase3_kernel<<<grid, SCAN_BLK>>>();
    }
    scatter_kernel<<<(N_ADJ * NNZ_C + 255) / 256, 256>>>(adj_rows);

    // ---- s0 = x @ W + b ----
    gemm_bias_kernel<<<(N_NODES + BM - 1) / BM, 256>>>(x, W, b, N_NODES);

    int spmm_blocks = (N_NODES + 7) / 8;   // 8 warps (rows) per 256-thread block

    // step 0: s1 = spmm(seq[0], s0)
    spmm_csr_step_kernel<<<spmm_blocks, 256>>>(
        adj_cols, adj_vals, seq + 0, nullptr, nullptr,
        0, 0, 0, 1, /*dst_id=*/1, nullptr, 0, gamma, beta);

    // step 1: s2 = spmm(seq[1], s1) + spmm(res[0], s0)
    spmm_csr_step_kernel<<<spmm_blocks, 256>>>(
        adj_cols, adj_vals, seq + 1, res + 0, nullptr,
        1, 0, 0, 2, /*dst_id=*/2, nullptr, 0, gamma, beta);

    // step 2 (+LN+GELU): out = ln_gelu( spmm(seq[2], s2) + spmm(res[1], s0)
    //                                   + spmm(res[2], s1) )
    spmm_csr_step_kernel<<<spmm_blocks, 256>>>(
        adj_cols, adj_vals, seq + 2, res + 1, res + 2,
        2, 0, 1, 3, /*dst_id=*/0, out, 1, gamma, beta);
}

// round 6
// speedup vs baseline: 2.2526x; 1.2267x over previous
#include <cuda_runtime.h>
#include <math.h>
#include <stdint.h>

// Problem constants (fixed by reference)
#define N_NODES 50000
#define N_HPREV 256
#define N_HID   128
#define NNZ_C   800000
#define N_ADJ   6
#define LN_EPS  1e-5f

#define SCAN_BLK 1024
#define NCHUNK   ((N_NODES + SCAN_BLK - 1) / SCAN_BLK)   // 49

// ---------------------------------------------------------------------------
// Scratch (device globals; referenced ONLY from device code)
// ---------------------------------------------------------------------------
__device__ __align__(16) float g_s0[(size_t)N_NODES * N_HID];   // 25.6 MB
__device__ __align__(16) float g_s1[(size_t)N_NODES * N_HID];   // 25.6 MB
__device__ __align__(16) float g_s2[(size_t)N_NODES * N_HID];   // 25.6 MB

__device__ int g_ptr [N_ADJ * (N_NODES + 1)];   // CSR row pointers
__device__ int g_fill[N_ADJ * N_NODES];         // histogram, then scatter cursors
__device__ int g_bsum[N_ADJ * NCHUNK];          // per-chunk scan sums
__device__ __align__(16) int2 g_cvr[(size_t)N_ADJ * NNZ_C];   // CSR (col,val) 38.4 MB

__device__ __forceinline__ float* state_ptr(int s) {
    switch (s) {
        case 0:  return g_s0;
        case 1:  return g_s1;
        default: return g_s2;
    }
}

// ---------------------------------------------------------------------------
// phase 0: zero the histogram (g_fill doubles as cnt)
// ---------------------------------------------------------------------------
__global__ __launch_bounds__(256) void zero_cnt_kernel() {
    int i = blockIdx.x * blockDim.x + threadIdx.x;
    if (i * 4 < N_ADJ * N_NODES) {
        int4 z = make_int4(0, 0, 0, 0);
        // N_ADJ*N_NODES = 300000, divisible by 4
        reinterpret_cast<int4*>(g_fill)[i] = z;
    }
}

// ---------------------------------------------------------------------------
// Fused GEMM + histogram (independent work overlapped in one launch).
//   blocks [0, GEMM_BLOCKS):         g_s0 = x @ W + b
//   blocks [GEMM_BLOCKS, ...):       histogram adj_rows into g_fill
// ---------------------------------------------------------------------------
#define BM 128
#define BK 32
#define GEMM_BLOCKS ((N_NODES + BM - 1) / BM)              // 391
#define HIST_BLOCKS ((N_ADJ * NNZ_C + 255) / 256)          // 18750

__global__ __launch_bounds__(256) void gemm_hist_kernel(
    const float* __restrict__ A, const float* __restrict__ W,
    const float* __restrict__ bias, const int* __restrict__ rows)
{
    __shared__ float As[BM][BK + 4];
    __shared__ float Bs[BK][N_HID];

    if (blockIdx.x >= GEMM_BLOCKS) {
        // ---------------- histogram path ----------------
        int e = (blockIdx.x - GEMM_BLOCKS) * 256 + threadIdx.x;
        if (e < N_ADJ * NNZ_C) {
            int a = e / NNZ_C;
            int r = __ldg(rows + e);
            atomicAdd(&g_fill[a * N_NODES + r], 1);
        }
        return;
    }

    // ---------------- GEMM path ----------------
    int tid  = threadIdx.x;
    int row0 = blockIdx.x * BM;

    int tx = tid & 15;
    int ty = tid >> 4;

    float acc[8][8];
#pragma unroll
    for (int i = 0; i < 8; ++i)
#pragma unroll
        for (int j = 0; j < 8; ++j) acc[i][j] = 0.f;

    int am = tid >> 3;
    int ak = (tid & 7) * 4;
    int bk = tid >> 5;
    int bn = (tid & 31) * 4;

    for (int k0 = 0; k0 < N_HPREV; k0 += BK) {
#pragma unroll
        for (int mm = 0; mm < BM; mm += 32) {
            int gr = row0 + am + mm;
            float4 v = make_float4(0.f, 0.f, 0.f, 0.f);
            if (gr < N_NODES)
                v = *reinterpret_cast<const float4*>(A + (size_t)gr * N_HPREV + k0 + ak);
            *reinterpret_cast<float4*>(&As[am + mm][ak]) = v;
        }
#pragma unroll
        for (int kk = 0; kk < BK; kk += 8) {
            float4 v = *reinterpret_cast<const float4*>(
                W + (size_t)(k0 + bk + kk) * N_HID + bn);
            *reinterpret_cast<float4*>(&Bs[bk + kk][bn]) = v;
        }
        __syncthreads();

#pragma unroll
        for (int k = 0; k < BK; ++k) {
            float a[8], bb[8];
#pragma unroll
            for (int i = 0; i < 8; ++i) a[i] = As[ty * 8 + i][k];
            float4 b0 = *reinterpret_cast<float4*>(&Bs[k][tx * 8]);
            float4 b1 = *reinterpret_cast<float4*>(&Bs[k][tx * 8 + 4]);
            bb[0] = b0.x; bb[1] = b0.y; bb[2] = b0.z; bb[3] = b0.w;
            bb[4] = b1.x; bb[5] = b1.y; bb[6] = b1.z; bb[7] = b1.w;
#pragma unroll
            for (int i = 0; i < 8; ++i)
#pragma unroll
                for (int j = 0; j < 8; ++j) acc[i][j] += a[i] * bb[j];
        }
        __syncthreads();
    }

    float4 bia0 = *reinterpret_cast<const float4*>(bias + tx * 8);
    float4 bia1 = *reinterpret_cast<const float4*>(bias + tx * 8 + 4);
    float bi[8] = {bia0.x, bia0.y, bia0.z, bia0.w, bia1.x, bia1.y, bia1.z, bia1.w};

#pragma unroll
    for (int i = 0; i < 8; ++i) {
        int gr = row0 + ty * 8 + i;
        if (gr < N_NODES) {
            float4 o0 = make_float4(acc[i][0] + bi[0], acc[i][1] + bi[1],
                                    acc[i][2] + bi[2], acc[i][3] + bi[3]);
            float4 o1 = make_float4(acc[i][4] + bi[4], acc[i][5] + bi[5],
                                    acc[i][6] + bi[6], acc[i][7] + bi[7]);
            *reinterpret_cast<float4*>(g_s0 + (size_t)gr * N_HID + tx * 8)     = o0;
            *reinterpret_cast<float4*>(g_s0 + (size_t)gr * N_HID + tx * 8 + 4) = o1;
        }
    }
}

// ---------------------------------------------------------------------------
// phase 2: per-chunk inclusive scan of counts (shfl two-level, 2 barriers)
// ---------------------------------------------------------------------------
__global__ __launch_bounds__(SCAN_BLK) void scan_phase1_kernel() {
    __shared__ int wsum[SCAN_BLK / 32];
    int a     = blockIdx.y;
    int chunk = blockIdx.x;
    int tid   = threadIdx.x;
    int lane  = tid & 31;
    int wrp   = tid >> 5;
    int i     = chunk * SCAN_BLK + tid;

    int v = (i < N_NODES) ? g_fill[a * N_NODES + i] : 0;

    // warp inclusive scan
    int inc = v;
#pragma unroll
    for (int off = 1; off < 32; off <<= 1) {
        int t = __shfl_up_sync(0xFFFFFFFFu, inc, off);
        if (lane >= off) inc += t;
    }
    if (lane == 31) wsum[wrp] = inc;
    __syncthreads();

    // warp 0 scans the 32 warp sums
    if (wrp == 0) {
        int s = wsum[lane];
        int si = s;
#pragma unroll
        for (int off = 1; off < 32; off <<= 1) {
            int t = __shfl_up_sync(0xFFFFFFFFu, si, off);
            if (lane >= off) si += t;
        }
        wsum[lane] = si - s;   // exclusive offset for each warp
    }
    __syncthreads();

    int incl = inc + wsum[wrp];
    if (i < N_NODES) g_ptr[a * (N_NODES + 1) + i] = incl;     // inclusive partial
    if (tid == SCAN_BLK - 1) g_bsum[a * NCHUNK + chunk] = incl;
}

// ---------------------------------------------------------------------------
// phase 3: exclusive scan of chunk sums (warp per adjacency)
// ---------------------------------------------------------------------------
__global__ void scan_phase2_kernel() {
    int a    = threadIdx.x >> 5;
    int lane = threadIdx.x & 31;
    if (a >= N_ADJ) return;
    int run = 0;
    for (int base = 0; base < NCHUNK; base += 32) {
        int i = base + lane;
        int v = (i < NCHUNK) ? g_bsum[a * NCHUNK + i] : 0;
        int inc = v;
#pragma unroll
        for (int off = 1; off < 32; off <<= 1) {
            int t = __shfl_up_sync(0xFFFFFFFFu, inc, off);
            if (lane >= off) inc += t;
        }
        if (i < NCHUNK) g_bsum[a * NCHUNK + i] = inc - v + run;   // exclusive
        run += __shfl_sync(0xFFFFFFFFu, inc, 31);
    }
}

// ---------------------------------------------------------------------------
// phase 4: finalize exclusive row pointers + init scatter cursors
// ---------------------------------------------------------------------------
__global__ __launch_bounds__(SCAN_BLK) void scan_phase3_kernel() {
    int a     = blockIdx.y;
    int chunk = blockIdx.x;
    int tid   = threadIdx.x;
    int i     = chunk * SCAN_BLK + tid;
    if (i < N_NODES) {
        int incl = g_ptr[a * (N_NODES + 1) + i];
        int cnt  = g_fill[a * N_NODES + i];
        int excl = incl - cnt + g_bsum[a * NCHUNK + chunk];
        g_ptr [a * (N_NODES + 1) + i] = excl;
        g_fill[a * N_NODES + i]       = excl;
    }
    if (blockIdx.x == 0 && tid == 0)
        g_ptr[a * (N_NODES + 1) + N_NODES] = NNZ_C;
}

// ---------------------------------------------------------------------------
// phase 5: scatter (col, val) into materialized CSR order (int2, 8B/nnz)
// ---------------------------------------------------------------------------
__global__ __launch_bounds__(256) void scatter_kernel(
    const int* __restrict__ rows, const int* __restrict__ cols,
    const float* __restrict__ vals)
{
    int e = blockIdx.x * blockDim.x + threadIdx.x;
    if (e >= N_ADJ * NNZ_C) return;
    int a = e / NNZ_C;
    int r = __ldg(rows + e);
    int pos = atomicAdd(&g_fill[a * N_NODES + r], 1);
    g_cvr[(size_t)a * NNZ_C + pos] = make_int2(__ldg(cols + e),
                                               __float_as_int(__ldg(vals + e)));
}

// ---------------------------------------------------------------------------
// CSR SpMM step: warp per output row, register accumulate, single store.
// Destination: state buffer (dst_id, resolved in-kernel) or final_out with
// fused LayerNorm + exact-erf GELU when do_ln != 0.
// ---------------------------------------------------------------------------
__device__ __forceinline__ float gelu_exact(float x) {
    return 0.5f * x * (1.f + erff(x * 0.70710678118654752440f));
}

__global__ __launch_bounds__(256) void spmm_csr_step_kernel(
    const int* idxp0, const int* idxp1, const int* idxp2,
    int src0, int src1, int src2, int n_terms,
    int dst_id,                         // used when do_ln == 0
    float* __restrict__ final_out,      // used when do_ln == 1 (harness d_out)
    int do_ln,
    const float* __restrict__ gamma, const float* __restrict__ beta)
{
    int row  = blockIdx.x * (blockDim.x >> 5) + (threadIdx.x >> 5);
    int lane = threadIdx.x & 31;
    if (row >= N_NODES) return;

    float4 acc = make_float4(0.f, 0.f, 0.f, 0.f);

#pragma unroll 1
    for (int t = 0; t < n_terms; ++t) {
        const int* idxp = (t == 0) ? idxp0 : ((t == 1) ? idxp1 : idxp2);
        int srcid       = (t == 0) ? src0  : ((t == 1) ? src1  : src2);
        int a = __ldg(idxp);
        const float* __restrict__ src = state_ptr(srcid);
        const int2*  __restrict__ cv  = g_cvr + (size_t)a * NNZ_C;

        int s = __ldg(&g_ptr[a * (N_NODES + 1) + row]);
        int e = __ldg(&g_ptr[a * (N_NODES + 1) + row + 1]);

        for (int base = s; base < e; base += 32) {
            int j = base + lane;
            int   c = 0;
            float v = 0.f;
            if (j < e) {
                int2 t2 = __ldg(cv + j);
                c = t2.x;
                v = __int_as_float(t2.y);
            }
            int m = min(32, e - base);
#pragma unroll 4
            for (int k = 0; k < m; ++k) {
                int   ck = __shfl_sync(0xFFFFFFFFu, c, k);
                float vk = __shfl_sync(0xFFFFFFFFu, v, k);
                float4 xv = *reinterpret_cast<const float4*>(
                    src + (size_t)ck * N_HID + lane * 4);
                acc.x += vk * xv.x;
                acc.y += vk * xv.y;
                acc.z += vk * xv.z;
                acc.w += vk * xv.w;
            }
        }
    }

    if (do_ln) {
        float s  = acc.x + acc.y + acc.z + acc.w;
        float sq = acc.x * acc.x + acc.y * acc.y + acc.z * acc.z + acc.w * acc.w;
#pragma unroll
        for (int o = 16; o > 0; o >>= 1) {
            s  += __shfl_xor_sync(0xFFFFFFFFu, s, o);
            sq += __shfl_xor_sync(0xFFFFFFFFu, sq, o);
        }
        float mu  = s * (1.f / N_HID);
        float var = sq * (1.f / N_HID) - mu * mu;
        float rs  = rsqrtf(var + LN_EPS);

        float4 g  = *reinterpret_cast<const float4*>(gamma + lane * 4);
        float4 be = *reinterpret_cast<const float4*>(beta  + lane * 4);

        float4 o;
        o.x = gelu_exact((acc.x - mu) * rs * g.x + be.x);
        o.y = gelu_exact((acc.y - mu) * rs * g.y + be.y);
        o.z = gelu_exact((acc.z - mu) * rs * g.z + be.z);
        o.w = gelu_exact((acc.w - mu) * rs * g.w + be.w);
        *reinterpret_cast<float4*>(final_out + (size_t)row * N_HID + lane * 4) = o;
    } else {
        float* dst = state_ptr(dst_id);
        *reinterpret_cast<float4*>(dst + (size_t)row * N_HID + lane * 4) = acc;
    }
}

// ---------------------------------------------------------------------------
// Launch
// inputs: 0:x 1:adj_rows 2:adj_cols 3:adj_vals 4:idxes_seq 5:idxes_res
//         6:W 7:b 8:gamma 9:beta        out: [50000,128] f32
// ---------------------------------------------------------------------------
extern "C" void kernel_launch(void* const* d_in, const int* in_sizes, int n_in,
                              void* d_out, int out_size)
{
    const float* x        = (const float*)d_in[0];
    const int*   adj_rows = (const int*)  d_in[1];
    const int*   adj_cols = (const int*)  d_in[2];
    const float* adj_vals = (const float*)d_in[3];
    const int*   seq      = (const int*)  d_in[4];
    const int*   res      = (const int*)  d_in[5];
    const float* W        = (const float*)d_in[6];
    const float* b        = (const float*)d_in[7];
    const float* gamma    = (const float*)d_in[8];
    const float* beta     = (const float*)d_in[9];
    float*       out      = (float*)d_out;

    // zero histogram (300000 ints = 75000 int4)
    zero_cnt_kernel<<<(N_ADJ * N_NODES / 4 + 255) / 256, 256>>>();

    // fused: GEMM (s0 = x@W + b) overlapped with row histogram
    gemm_hist_kernel<<<GEMM_BLOCKS + HIST_BLOCKS, 256>>>(x, W, b, adj_rows);

    // CSR row pointers
    {
        dim3 grid(NCHUNK, N_ADJ);
        scan_phase1_kernel<<<grid, SCAN_BLK>>>();
        scan_phase2_kernel<<<1, N_ADJ * 32>>>();
        scan_phase3_kernel<<<grid, SCAN_BLK>>>();
    }
    // materialize CSR (col,val)
    scatter_kernel<<<(N_ADJ * NNZ_C + 255) / 256, 256>>>(adj_rows, adj_cols, adj_vals);

    int spmm_blocks = (N_NODES + 7) / 8;   // 8 warps (rows) per 256-thread block

    // step 0: s1 = spmm(seq[0], s0)
    spmm_csr_step_kernel<<<spmm_blocks, 256>>>(
        seq + 0, nullptr, nullptr,
        0, 0, 0, 1, /*dst_id=*/1, nullptr, 0, gamma, beta);

    // step 1: s2 = spmm(seq[1], s1) + spmm(res[0], s0)
    spmm_csr_step_kernel<<<spmm_blocks, 256>>>(
        seq + 1, res + 0, nullptr,
        1, 0, 0, 2, /*dst_id=*/2, nullptr, 0, gamma, beta);

    // step 2 (+LN+GELU): out = ln_gelu( spmm(seq[2], s2) + spmm(res[1], s0)
    //                                   + spmm(res[2], s1) )
    spmm_csr_step_kernel<<<spmm_blocks, 256>>>(
        seq + 2, res + 1, res + 2,
        2, 0, 1, 3, /*dst_id=*/0, out, 1, gamma, beta);
}

// round 7
// speedup vs baseline: 2.4869x; 1.1040x over previous
#include <cuda_runtime.h>
#include <cuda_fp16.h>
#include <math.h>
#include <stdint.h>

// Problem constants (fixed by reference)
#define N_NODES 50000
#define N_HPREV 256
#define N_HID   128
#define NNZ_C   800000
#define N_ADJ   6
#define LN_EPS  1e-5f

#define SCAN_BLK 1024
#define NCHUNK   ((N_NODES + SCAN_BLK - 1) / SCAN_BLK)   // 49

// ---------------------------------------------------------------------------
// Scratch (device globals; referenced ONLY from device code)
// States stored fp16 (accumulation is fp32 in registers; storage-only rounding)
// ---------------------------------------------------------------------------
__device__ __align__(16) __half g_s0[(size_t)N_NODES * N_HID];   // 12.8 MB
__device__ __align__(16) __half g_s1[(size_t)N_NODES * N_HID];   // 12.8 MB
__device__ __align__(16) __half g_s2[(size_t)N_NODES * N_HID];   // 12.8 MB

__device__ int g_ptr [N_ADJ * (N_NODES + 1)];   // CSR row pointers
__device__ int g_fill[N_ADJ * N_NODES];         // histogram, then scatter cursors
__device__ int g_bsum[N_ADJ * NCHUNK];          // per-chunk scan sums
__device__ __align__(16) int2 g_cvr[(size_t)N_ADJ * NNZ_C];   // CSR (col,val) 38.4 MB

__device__ __forceinline__ __half* state_ptr(int s) {
    switch (s) {
        case 0:  return g_s0;
        case 1:  return g_s1;
        default: return g_s2;
    }
}

// ---------------------------------------------------------------------------
// phase 0: zero the histogram (g_fill doubles as cnt)
// ---------------------------------------------------------------------------
__global__ __launch_bounds__(256) void zero_cnt_kernel() {
    int i = blockIdx.x * blockDim.x + threadIdx.x;
    if (i * 4 < N_ADJ * N_NODES) {
        int4 z = make_int4(0, 0, 0, 0);
        reinterpret_cast<int4*>(g_fill)[i] = z;   // 300000 divisible by 4
    }
}

// ---------------------------------------------------------------------------
// Fused GEMM + histogram (independent work overlapped in one launch).
//   blocks [0, GEMM_BLOCKS):   g_s0 = half(x @ W + b)
//   blocks [GEMM_BLOCKS, ...): histogram adj_rows into g_fill
// ---------------------------------------------------------------------------
#define BM 128
#define BK 32
#define GEMM_BLOCKS ((N_NODES + BM - 1) / BM)              // 391
#define HIST_BLOCKS ((N_ADJ * NNZ_C + 255) / 256)          // 18750

__global__ __launch_bounds__(256) void gemm_hist_kernel(
    const float* __restrict__ A, const float* __restrict__ W,
    const float* __restrict__ bias, const int* __restrict__ rows)
{
    __shared__ float As[BM][BK + 4];
    __shared__ float Bs[BK][N_HID];

    if (blockIdx.x >= GEMM_BLOCKS) {
        // ---------------- histogram path ----------------
        int e = (blockIdx.x - GEMM_BLOCKS) * 256 + threadIdx.x;
        if (e < N_ADJ * NNZ_C) {
            int a = e / NNZ_C;
            int r = __ldg(rows + e);
            atomicAdd(&g_fill[a * N_NODES + r], 1);
        }
        return;
    }

    // ---------------- GEMM path ----------------
    int tid  = threadIdx.x;
    int row0 = blockIdx.x * BM;

    int tx = tid & 15;
    int ty = tid >> 4;

    float acc[8][8];
#pragma unroll
    for (int i = 0; i < 8; ++i)
#pragma unroll
        for (int j = 0; j < 8; ++j) acc[i][j] = 0.f;

    int am = tid >> 3;
    int ak = (tid & 7) * 4;
    int bk = tid >> 5;
    int bn = (tid & 31) * 4;

    for (int k0 = 0; k0 < N_HPREV; k0 += BK) {
#pragma unroll
        for (int mm = 0; mm < BM; mm += 32) {
            int gr = row0 + am + mm;
            float4 v = make_float4(0.f, 0.f, 0.f, 0.f);
            if (gr < N_NODES)
                v = *reinterpret_cast<const float4*>(A + (size_t)gr * N_HPREV + k0 + ak);
            *reinterpret_cast<float4*>(&As[am + mm][ak]) = v;
        }
#pragma unroll
        for (int kk = 0; kk < BK; kk += 8) {
            float4 v = *reinterpret_cast<const float4*>(
                W + (size_t)(k0 + bk + kk) * N_HID + bn);
            *reinterpret_cast<float4*>(&Bs[bk + kk][bn]) = v;
        }
        __syncthreads();

#pragma unroll
        for (int k = 0; k < BK; ++k) {
            float a[8], bb[8];
#pragma unroll
            for (int i = 0; i < 8; ++i) a[i] = As[ty * 8 + i][k];
            float4 b0 = *reinterpret_cast<float4*>(&Bs[k][tx * 8]);
            float4 b1 = *reinterpret_cast<float4*>(&Bs[k][tx * 8 + 4]);
            bb[0] = b0.x; bb[1] = b0.y; bb[2] = b0.z; bb[3] = b0.w;
            bb[4] = b1.x; bb[5] = b1.y; bb[6] = b1.z; bb[7] = b1.w;
#pragma unroll
            for (int i = 0; i < 8; ++i)
#pragma unroll
                for (int j = 0; j < 8; ++j) acc[i][j] += a[i] * bb[j];
        }
        __syncthreads();
    }

    float4 bia0 = *reinterpret_cast<const float4*>(bias + tx * 8);
    float4 bia1 = *reinterpret_cast<const float4*>(bias + tx * 8 + 4);
    float bi[8] = {bia0.x, bia0.y, bia0.z, bia0.w, bia1.x, bia1.y, bia1.z, bia1.w};

#pragma unroll
    for (int i = 0; i < 8; ++i) {
        int gr = row0 + ty * 8 + i;
        if (gr < N_NODES) {
            __half2 h[4];
            h[0] = __floats2half2_rn(acc[i][0] + bi[0], acc[i][1] + bi[1]);
            h[1] = __floats2half2_rn(acc[i][2] + bi[2], acc[i][3] + bi[3]);
            h[2] = __floats2half2_rn(acc[i][4] + bi[4], acc[i][5] + bi[5]);
            h[3] = __floats2half2_rn(acc[i][6] + bi[6], acc[i][7] + bi[7]);
            *reinterpret_cast<uint4*>(g_s0 + (size_t)gr * N_HID + tx * 8) =
                *reinterpret_cast<uint4*>(h);
        }
    }
}

// ---------------------------------------------------------------------------
// phase 2: per-chunk inclusive scan of counts (shfl two-level)
// ---------------------------------------------------------------------------
__global__ __launch_bounds__(SCAN_BLK) void scan_phase1_kernel() {
    __shared__ int wsum[SCAN_BLK / 32];
    int a     = blockIdx.y;
    int chunk = blockIdx.x;
    int tid   = threadIdx.x;
    int lane  = tid & 31;
    int wrp   = tid >> 5;
    int i     = chunk * SCAN_BLK + tid;

    int v = (i < N_NODES) ? g_fill[a * N_NODES + i] : 0;

    int inc = v;
#pragma unroll
    for (int off = 1; off < 32; off <<= 1) {
        int t = __shfl_up_sync(0xFFFFFFFFu, inc, off);
        if (lane >= off) inc += t;
    }
    if (lane == 31) wsum[wrp] = inc;
    __syncthreads();

    if (wrp == 0) {
        int s = wsum[lane];
        int si = s;
#pragma unroll
        for (int off = 1; off < 32; off <<= 1) {
            int t = __shfl_up_sync(0xFFFFFFFFu, si, off);
            if (lane >= off) si += t;
        }
        wsum[lane] = si - s;
    }
    __syncthreads();

    int incl = inc + wsum[wrp];
    if (i < N_NODES) g_ptr[a * (N_NODES + 1) + i] = incl;     // inclusive partial
    if (tid == SCAN_BLK - 1) g_bsum[a * NCHUNK + chunk] = incl;
}

// ---------------------------------------------------------------------------
// phase 3: exclusive scan of chunk sums (warp per adjacency)
// ---------------------------------------------------------------------------
__global__ void scan_phase2_kernel() {
    int a    = threadIdx.x >> 5;
    int lane = threadIdx.x & 31;
    if (a >= N_ADJ) return;
    int run = 0;
    for (int base = 0; base < NCHUNK; base += 32) {
        int i = base + lane;
        int v = (i < NCHUNK) ? g_bsum[a * NCHUNK + i] : 0;
        int inc = v;
#pragma unroll
        for (int off = 1; off < 32; off <<= 1) {
            int t = __shfl_up_sync(0xFFFFFFFFu, inc, off);
            if (lane >= off) inc += t;
        }
        if (i < NCHUNK) g_bsum[a * NCHUNK + i] = inc - v + run;   // exclusive
        run += __shfl_sync(0xFFFFFFFFu, inc, 31);
    }
}

// ---------------------------------------------------------------------------
// phase 4: finalize exclusive row pointers + init scatter cursors
// ---------------------------------------------------------------------------
__global__ __launch_bounds__(SCAN_BLK) void scan_phase3_kernel() {
    int a     = blockIdx.y;
    int chunk = blockIdx.x;
    int tid   = threadIdx.x;
    int i     = chunk * SCAN_BLK + tid;
    if (i < N_NODES) {
        int incl = g_ptr[a * (N_NODES + 1) + i];
        int cnt  = g_fill[a * N_NODES + i];
        int excl = incl - cnt + g_bsum[a * NCHUNK + chunk];
        g_ptr [a * (N_NODES + 1) + i] = excl;
        g_fill[a * N_NODES + i]       = excl;
    }
    if (blockIdx.x == 0 && tid == 0)
        g_ptr[a * (N_NODES + 1) + N_NODES] = NNZ_C;
}

// ---------------------------------------------------------------------------
// phase 5: scatter (col, val) into materialized CSR order (int2, 8B/nnz)
// ---------------------------------------------------------------------------
__global__ __launch_bounds__(256) void scatter_kernel(
    const int* __restrict__ rows, const int* __restrict__ cols,
    const float* __restrict__ vals)
{
    int e = blockIdx.x * blockDim.x + threadIdx.x;
    if (e >= N_ADJ * NNZ_C) return;
    int a = e / NNZ_C;
    int r = __ldg(rows + e);
    int pos = atomicAdd(&g_fill[a * N_NODES + r], 1);
    g_cvr[(size_t)a * NNZ_C + pos] = make_int2(__ldg(cols + e),
                                               __float_as_int(__ldg(vals + e)));
}

// ---------------------------------------------------------------------------
// CSR SpMM step: warp per output row, fp32 register accumulate over fp16
// source states, single store (fp16 state or fp32 final with fused LN+GELU).
// ---------------------------------------------------------------------------
__device__ __forceinline__ float gelu_exact(float x) {
    return 0.5f * x * (1.f + erff(x * 0.70710678118654752440f));
}

__global__ __launch_bounds__(256) void spmm_csr_step_kernel(
    const int* idxp0, const int* idxp1, const int* idxp2,
    int src0, int src1, int src2, int n_terms,
    int dst_id,                         // used when do_ln == 0
    float* __restrict__ final_out,      // used when do_ln == 1 (harness d_out)
    int do_ln,
    const float* __restrict__ gamma, const float* __restrict__ beta)
{
    int row  = blockIdx.x * (blockDim.x >> 5) + (threadIdx.x >> 5);
    int lane = threadIdx.x & 31;
    if (row >= N_NODES) return;

    float4 acc = make_float4(0.f, 0.f, 0.f, 0.f);

#pragma unroll 1
    for (int t = 0; t < n_terms; ++t) {
        const int* idxp = (t == 0) ? idxp0 : ((t == 1) ? idxp1 : idxp2);
        int srcid       = (t == 0) ? src0  : ((t == 1) ? src1  : src2);
        int a = __ldg(idxp);
        const __half* __restrict__ src = state_ptr(srcid);
        const int2*   __restrict__ cv  = g_cvr + (size_t)a * NNZ_C;

        int s = __ldg(&g_ptr[a * (N_NODES + 1) + row]);
        int e = __ldg(&g_ptr[a * (N_NODES + 1) + row + 1]);

        for (int base = s; base < e; base += 32) {
            int j = base + lane;
            int   c = 0;
            float v = 0.f;
            if (j < e) {
                int2 t2 = __ldg(cv + j);
                c = t2.x;
                v = __int_as_float(t2.y);
            }
            int m = min(32, e - base);
#pragma unroll 4
            for (int k = 0; k < m; ++k) {
                int   ck = __shfl_sync(0xFFFFFFFFu, c, k);
                float vk = __shfl_sync(0xFFFFFFFFu, v, k);
                // 4 halves (8 B) per lane: cols [4*lane, 4*lane+4)
                uint2 raw = *reinterpret_cast<const uint2*>(
                    src + (size_t)ck * N_HID + lane * 4);
                float2 x0 = __half22float2(*reinterpret_cast<__half2*>(&raw.x));
                float2 x1 = __half22float2(*reinterpret_cast<__half2*>(&raw.y));
                acc.x += vk * x0.x;
                acc.y += vk * x0.y;
                acc.z += vk * x1.x;
                acc.w += vk * x1.y;
            }
        }
    }

    if (do_ln) {
        float s  = acc.x + acc.y + acc.z + acc.w;
        float sq = acc.x * acc.x + acc.y * acc.y + acc.z * acc.z + acc.w * acc.w;
#pragma unroll
        for (int o = 16; o > 0; o >>= 1) {
            s  += __shfl_xor_sync(0xFFFFFFFFu, s, o);
            sq += __shfl_xor_sync(0xFFFFFFFFu, sq, o);
        }
        float mu  = s * (1.f / N_HID);
        float var = sq * (1.f / N_HID) - mu * mu;
        float rs  = rsqrtf(var + LN_EPS);

        float4 g  = *reinterpret_cast<const float4*>(gamma + lane * 4);
        float4 be = *reinterpret_cast<const float4*>(beta  + lane * 4);

        float4 o;
        o.x = gelu_exact((acc.x - mu) * rs * g.x + be.x);
        o.y = gelu_exact((acc.y - mu) * rs * g.y + be.y);
        o.z = gelu_exact((acc.z - mu) * rs * g.z + be.z);
        o.w = gelu_exact((acc.w - mu) * rs * g.w + be.w);
        *reinterpret_cast<float4*>(final_out + (size_t)row * N_HID + lane * 4) = o;
    } else {
        __half* dst = state_ptr(dst_id);
        __half2 h0 = __floats2half2_rn(acc.x, acc.y);
        __half2 h1 = __floats2half2_rn(acc.z, acc.w);
        uint2 packed;
        packed.x = *reinterpret_cast<uint32_t*>(&h0);
        packed.y = *reinterpret_cast<uint32_t*>(&h1);
        *reinterpret_cast<uint2*>(dst + (size_t)row * N_HID + lane * 4) = packed;
    }
}

// ---------------------------------------------------------------------------
// Launch
// inputs: 0:x 1:adj_rows 2:adj_cols 3:adj_vals 4:idxes_seq 5:idxes_res
//         6:W 7:b 8:gamma 9:beta        out: [50000,128] f32
// ---------------------------------------------------------------------------
extern "C" void kernel_launch(void* const* d_in, const int* in_sizes, int n_in,
                              void* d_out, int out_size)
{
    const float* x        = (const float*)d_in[0];
    const int*   adj_rows = (const int*)  d_in[1];
    const int*   adj_cols = (const int*)  d_in[2];
    const float* adj_vals = (const float*)d_in[3];
    const int*   seq      = (const int*)  d_in[4];
    const int*   res      = (const int*)  d_in[5];
    const float* W        = (const float*)d_in[6];
    const float* b        = (const float*)d_in[7];
    const float* gamma    = (const float*)d_in[8];
    const float* beta     = (const float*)d_in[9];
    float*       out      = (float*)d_out;

    // zero histogram
    zero_cnt_kernel<<<(N_ADJ * N_NODES / 4 + 255) / 256, 256>>>();

    // fused: GEMM (s0 = x@W + b, fp16 store) overlapped with row histogram
    gemm_hist_kernel<<<GEMM_BLOCKS + HIST_BLOCKS, 256>>>(x, W, b, adj_rows);

    // CSR row pointers
    {
        dim3 grid(NCHUNK, N_ADJ);
        scan_phase1_kernel<<<grid, SCAN_BLK>>>();
        scan_phase2_kernel<<<1, N_ADJ * 32>>>();
        scan_phase3_kernel<<<grid, SCAN_BLK>>>();
    }
    // materialize CSR (col,val)
    scatter_kernel<<<(N_ADJ * NNZ_C + 255) / 256, 256>>>(adj_rows, adj_cols, adj_vals);

    int spmm_blocks = (N_NODES + 7) / 8;   // 8 warps (rows) per 256-thread block

    // step 0: s1 = spmm(seq[0], s0)
    spmm_csr_step_kernel<<<spmm_blocks, 256>>>(
        seq + 0, nullptr, nullptr,
        0, 0, 0, 1, /*dst_id=*/1, nullptr, 0, gamma, beta);

    // step 1: s2 = spmm(seq[1], s1) + spmm(res[0], s0)
    spmm_csr_step_kernel<<<spmm_blocks, 256>>>(
        seq + 1, res + 0, nullptr,
        1, 0, 0, 2, /*dst_id=*/2, nullptr, 0, gamma, beta);

    // step 2 (+LN+GELU): out = ln_gelu( spmm(seq[2], s2) + spmm(res[1], s0)
    //                                   + spmm(res[2], s1) )
    spmm_csr_step_kernel<<<spmm_blocks, 256>>>(
        seq + 2, res + 1, res + 2,
        2, 0, 1, 3, /*dst_id=*/0, out, 1, gamma, beta);
}